// round 6
// baseline (speedup 1.0000x reference)
#include <cuda_runtime.h>

// Sliding-window minimum, window = [t, t+256] (257 elems), 'last' padding.
// out[b,t] = min_{i=t..t+256} sig[b, min(i, T-1)]
//
// Warp-autonomous chunk-32 decomposition (NO shared memory, NO barriers):
// window 257 = (32-m) + 7*32 + (m+1) for phase m = lane.
//   head   = suffix-min of x0 within the warp        (5 predicated SHFLs)
//   middle = min over the 7 full chunks = warp-min of per-lane min(x1..x7)
//            (3-deep fmin tree + 5-step XOR butterfly)
//   tail   = prefix-min of x8 within the warp        (5 predicated SHFLs)
// where x_k = sig[clamp(t + 32k)]. 9 front-batched LDGs per thread (MLP=9).

#define BT 256  // threads per block (8 independent warps, 256 outputs)

__global__ __launch_bounds__(BT) void always_window_min(
    const float* __restrict__ sig, float* __restrict__ out, int T)
{
    const int b    = blockIdx.y;
    const int t    = blockIdx.x * BT + threadIdx.x;   // output index
    const int lane = threadIdx.x & 31;

    const float* row = sig + (size_t)b * T;

    // 9 clamped loads covering [t, t+288) at stride 32 — front-batched.
    float x[9];
    #pragma unroll
    for (int k = 0; k < 9; k++) {
        int g = t + 32 * k;
        g = g < T - 1 ? g : T - 1;            // 'last' padding clamp
        x[k] = __ldg(row + g);
    }

    // Head: warp suffix-min of x0 (covers lanes lane..31 of own chunk).
    // Tail: warp prefix-min of x8 (covers lanes 0..lane of chunk c+8).
    float suf = x[0], pre = x[8];
    #pragma unroll
    for (int d = 1; d < 32; d <<= 1) {
        float dn = __shfl_down_sync(0xffffffffu, suf, d);
        if (lane < 32 - d) suf = fminf(suf, dn);
        float up = __shfl_up_sync(0xffffffffu, pre, d);
        if (lane >= d) pre = fminf(pre, up);
    }

    // Middle: min over the union of full chunks c+1..c+7 =
    // warp-wide min of per-lane min(x1..x7).
    float m0 = fminf(x[1], x[2]);
    float m1 = fminf(x[3], x[4]);
    float m2 = fminf(x[5], x[6]);
    float mid = fminf(fminf(m0, m1), fminf(m2, x[7]));
    #pragma unroll
    for (int d = 16; d >= 1; d >>= 1)
        mid = fminf(mid, __shfl_xor_sync(0xffffffffu, mid, d));

    out[(size_t)b * T + t] = fminf(fminf(suf, mid), pre);
}

extern "C" void kernel_launch(void* const* d_in, const int* in_sizes, int n_in,
                              void* d_out, int out_size)
{
    const float* sig = (const float*)d_in[0];
    float* out = (float*)d_out;

    const int T = 8192;                      // per reference setup_inputs
    const int B = in_sizes[0] / T;           // = 4

    dim3 grid(T / BT, B);
    always_window_min<<<grid, BT>>>(sig, out, T);
}